// round 15
// baseline (speedup 1.0000x reference)
#include <cuda_runtime.h>

#define IMG 512
#define TW 256
#define TH 8
#define KS 11
#define HALO 5
#define COLS (TW + 2*HALO)   /* 266 */
#define S2 267               /* float2 row stride (odd -> conflict-free) */
#define NTHREADS 256
/* smem: s_v1 8*267*8 + s_vq 8*267*8 = 34176 B -> 4 CTAs/SM */
#define SMEM_BYTES (TH*S2*8*2)

typedef unsigned long long u64;

__device__ double g_accum;
__device__ float g_wv[2][KS];
__device__ float g_wh[2][KS];

__device__ __forceinline__ u64 pack2(float x, float y) {
    u64 r; asm("mov.b64 %0, {%1,%2};" : "=l"(r) : "f"(x), "f"(y)); return r;
}
__device__ __forceinline__ void unpack2(u64 v, float& x, float& y) {
    asm("mov.b64 {%0,%1}, %2;" : "=f"(x), "=f"(y) : "l"(v));
}
__device__ __forceinline__ u64 fma2(u64 a, u64 b, u64 c) {
    u64 d; asm("fma.rn.f32x2 %0, %1, %2, %3;" : "=l"(d) : "l"(a), "l"(b), "l"(c)); return d;
}

/* Gaussian symmetry w[k] == w[10-k] (bit-exact: k2 = g outer g) */
#define WIDX(k) ((k) < 6 ? (k) : 10 - (k))

// Rank-1 factor reconstruction; resets accumulator each replay.
__global__ void prep_kernel(const float* __restrict__ kern) {
    int tid = threadIdx.x;
    if (tid == 0) g_accum = 0.0;
    if (tid < 64) {
        int ch = tid >> 5, lane = tid & 31;
        const float* kc = kern + ch * KS * KS;
        float s = 0.f;
        if (lane < KS) {
            #pragma unroll
            for (int j = 0; j < KS; j++) s += kc[lane * KS + j];       // row sums
        } else if (lane < 2 * KS) {
            #pragma unroll
            for (int j = 0; j < KS; j++) s += kc[j * KS + lane - KS];  // col sums
        }
        float contrib = (lane < KS) ? s : 0.f;
        #pragma unroll
        for (int o = 16; o > 0; o >>= 1) contrib += __shfl_xor_sync(0xffffffffu, contrib, o);
        if (lane < KS)           g_wv[ch][lane] = s;
        else if (lane < 2 * KS)  g_wh[ch][lane - KS] = s / contrib;
    }
}

extern __shared__ float2 smem_dyn[];

/* accumulate one input px into R row accumulators (streams (x,y),(x^2+y^2,xy)) */
template<int R>
__device__ __forceinline__ void vacc(float vx, float vy, int tt,
                                     const u64* __restrict__ wv2,
                                     u64* a1, u64* aq) {
    u64 u = pack2(vx, vy);
    float s2  = fmaf(vy, vy, vx * vx);
    float pxy = vx * vy;
    u64 q = pack2(s2, pxy);
    #pragma unroll
    for (int i = 0; i < R; i++) {
        int k = tt - i;
        if (k >= 0 && k < KS) {
            int wi = WIDX(k);
            a1[i] = fma2(wv2[wi], u, a1[i]);
            aq[i] = fma2(wv2[wi], q, aq[i]);
        }
    }
}

/* one vertical-conv task: column m (tile-local), output rows [rg, rg+R) */
template<int R>
__device__ __forceinline__ void run_task(int m, int rg, int oh0, int ow0,
                                         const float* __restrict__ xp,
                                         const float* __restrict__ yp,
                                         const u64* __restrict__ wv2,
                                         float2* s_v1, float2* s_vq) {
    const int NR = R + KS - 1;
    int gc = ow0 + m - HALO;
    bool colok = (unsigned)gc < (unsigned)IMG;
    int r0 = oh0 + rg - HALO;
    bool rowok = (r0 >= 0) && (r0 + NR <= IMG);
    const float* xb = xp + (ptrdiff_t)r0 * IMG + gc;
    const float* yb = yp + (ptrdiff_t)r0 * IMG + gc;

    u64 a1[R], aq[R];
    #pragma unroll
    for (int i = 0; i < R; i++) { a1[i] = 0ull; aq[i] = 0ull; }

    if (colok && rowok) {
        #pragma unroll
        for (int tt = 0; tt < NR; tt++)            // unpredicated fast path
            vacc<R>(__ldg(xb + tt * IMG), __ldg(yb + tt * IMG), tt, wv2, a1, aq);
    } else {
        #pragma unroll
        for (int tt = 0; tt < NR; tt++) {
            int gr = r0 + tt;
            float vx = 0.f, vy = 0.f;
            if (colok && (unsigned)gr < (unsigned)IMG) {
                vx = __ldg(xb + tt * IMG);
                vy = __ldg(yb + tt * IMG);
            }
            vacc<R>(vx, vy, tt, wv2, a1, aq);
        }
    }
    #pragma unroll
    for (int i = 0; i < R; i++) {
        *reinterpret_cast<u64*>(&s_v1[(rg + i) * S2 + m]) = a1[i];
        *reinterpret_cast<u64*>(&s_vq[(rg + i) * S2 + m]) = aq[i];
    }
}

__global__ __launch_bounds__(NTHREADS, 4)
void ssim_main(const float* __restrict__ x, const float* __restrict__ y) {
    float2* s_v1 = smem_dyn;                  // [TH][S2] (sum_x, sum_y)
    float2* s_vq = s_v1 + TH * S2;            // [TH][S2] (sum_{x^2+y^2}, sum_xy)

    const int tid = threadIdx.x;
    const int plane = blockIdx.z;             // 64 = 32 batch * 2 chan (NCHW)
    const int ch = plane & 1;
    const int oh0 = blockIdx.y * TH;
    const int ow0 = blockIdx.x * TW;
    const float* xp = x + (size_t)plane * IMG * IMG;
    const float* yp = y + (size_t)plane * IMG * IMG;

    u64 wv2[6];
    #pragma unroll
    for (int k = 0; k < 6; k++) { float w = __ldg(&g_wv[ch][k]); wv2[k] = pack2(w, w); }

    // ---- stage 1: 266 cols x 1 rowgroup = 256 RG8 (1:1 threads) + 10 cols as 20 RG4 ----
    {
        run_task<8>(tid, 0, oh0, ow0, xp, yp, wv2, s_v1, s_vq);

        if (tid < 20) {                        // leftover cols 256..265, split rows 0-3/4-7
            int m2  = 256 + (tid >> 1);
            int rg2 = (tid & 1) * 4;
            run_task<4>(m2, rg2, oh0, ow0, xp, yp, wv2, s_v1, s_vq);
        }
    }

    __syncthreads();

    // ---- stage 2: horizontal conv, 8 px per thread (256 tasks = 256 threads) ----
    u64 wh2[6];
    #pragma unroll
    for (int k = 0; k < 6; k++) { float w = __ldg(&g_wh[ch][k]); wh2[k] = pack2(w, w); }

    const int row = tid & 7;                  // 8 rows; phase-conflict-free (534r+16g mod 32 distinct)
    const int c0 = (tid >> 3) * 8;            // 32 col groups * 8 = 256
    const float C1 = 1e-4f, C2 = 9e-4f;
    float lsum = 0.f;

    u64 h1[8], hq[8];
    #pragma unroll
    for (int p = 0; p < 8; p++) { h1[p] = 0ull; hq[p] = 0ull; }

    #pragma unroll
    for (int j = 0; j < 8 + KS - 1; j++) {    // 18 input cols shared across 8 px
        u64 b1 = *reinterpret_cast<const u64*>(&s_v1[row * S2 + c0 + j]);
        u64 bq = *reinterpret_cast<const u64*>(&s_vq[row * S2 + c0 + j]);
        #pragma unroll
        for (int p = 0; p < 8; p++) {
            int k = j - p;
            if (k >= 0 && k < KS) {
                int wi = WIDX(k);
                h1[p] = fma2(wh2[wi], b1, h1[p]);
                hq[p] = fma2(wh2[wi], bq, hq[p]);
            }
        }
    }

    // ---- epilogue: SSIM per pixel ----
    #pragma unroll
    for (int p = 0; p < 8; p++) {
        float mux, muy; unpack2(h1[p], mux, muy);
        float es, exy;  unpack2(hq[p], es, exy);     // es = E[x^2+y^2]
        float muxy = mux * muy;
        float sxy  = fmaf(-mux, muy, exy);
        float na   = fmaf(muxy, 2.0f, C1);
        float nb   = fmaf(sxy,  2.0f, C2);
        float m2   = fmaf(mux, mux, muy * muy);
        float dena = m2 + C1;
        float denb = (es - m2) + C2;
        lsum += __fdividef(na * nb, dena * denb);
    }

    // ---- reduction: warp -> block -> one double atomic ----
    #pragma unroll
    for (int o = 16; o > 0; o >>= 1) lsum += __shfl_xor_sync(0xffffffffu, lsum, o);
    __shared__ float wsum[NTHREADS / 32];
    if ((tid & 31) == 0) wsum[tid >> 5] = lsum;
    __syncthreads();
    if (tid == 0) {
        float b = 0.f;
        #pragma unroll
        for (int w = 0; w < NTHREADS / 32; w++) b += wsum[w];
        atomicAdd(&g_accum, (double)b);
    }
}

__global__ void finalize_kernel(float* __restrict__ out) {
    if (threadIdx.x == 0) {
        out[0] = 1.0f - (float)(g_accum * (1.0 / (32.0 * 2.0 * 512.0 * 512.0)));
    }
}

extern "C" void kernel_launch(void* const* d_in, const int* in_sizes, int n_in,
                              void* d_out, int out_size) {
    const float* x = (const float*)d_in[0];
    const float* y = (const float*)d_in[1];
    const float* kern = (const float*)d_in[2];
    float* out = (float*)d_out;

    prep_kernel<<<1, 64>>>(kern);
    dim3 grid(IMG / TW, IMG / TH, 64);
    ssim_main<<<grid, NTHREADS, SMEM_BYTES>>>(x, y);
    finalize_kernel<<<1, 32>>>(out);
}

// round 16
// speedup vs baseline: 1.2773x; 1.2773x over previous
#include <cuda_runtime.h>

#define IMG 512
#define TW 128
#define TH 16
#define KS 11
#define HALO 5
#define COLS (TW + 2*HALO)   /* 138 */
#define S2 139               /* float2 row stride (odd -> conflict-free) */
#define NTHREADS 256
/* smem: s_v1 16*139*8 + s_vq 16*139*8 = 35584 B -> 4 CTAs/SM */
#define SMEM_BYTES (TH*S2*8*2)

typedef unsigned long long u64;

__device__ double g_accum;
__device__ float g_wv[2][KS];
__device__ float g_wh[2][KS];

__device__ __forceinline__ u64 pack2(float x, float y) {
    u64 r; asm("mov.b64 %0, {%1,%2};" : "=l"(r) : "f"(x), "f"(y)); return r;
}
__device__ __forceinline__ void unpack2(u64 v, float& x, float& y) {
    asm("mov.b64 {%0,%1}, %2;" : "=f"(x), "=f"(y) : "l"(v));
}
__device__ __forceinline__ u64 fma2(u64 a, u64 b, u64 c) {
    u64 d; asm("fma.rn.f32x2 %0, %1, %2, %3;" : "=l"(d) : "l"(a), "l"(b), "l"(c)); return d;
}

/* Gaussian symmetry w[k] == w[10-k] (bit-exact: k2 = g outer g) */
#define WIDX(k) ((k) < 6 ? (k) : 10 - (k))

// Rank-1 factor reconstruction; resets accumulator each replay.
__global__ void prep_kernel(const float* __restrict__ kern) {
    int tid = threadIdx.x;
    if (tid == 0) g_accum = 0.0;
    if (tid < 64) {
        int ch = tid >> 5, lane = tid & 31;
        const float* kc = kern + ch * KS * KS;
        float s = 0.f;
        if (lane < KS) {
            #pragma unroll
            for (int j = 0; j < KS; j++) s += kc[lane * KS + j];       // row sums
        } else if (lane < 2 * KS) {
            #pragma unroll
            for (int j = 0; j < KS; j++) s += kc[j * KS + lane - KS];  // col sums
        }
        float contrib = (lane < KS) ? s : 0.f;
        #pragma unroll
        for (int o = 16; o > 0; o >>= 1) contrib += __shfl_xor_sync(0xffffffffu, contrib, o);
        if (lane < KS)           g_wv[ch][lane] = s;
        else if (lane < 2 * KS)  g_wh[ch][lane - KS] = s / contrib;
    }
}

extern __shared__ float2 smem_dyn[];

/* accumulate one input px into R row accumulators (streams (x,y),(x^2+y^2,xy)) */
template<int R>
__device__ __forceinline__ void vacc(float vx, float vy, int tt,
                                     const u64* __restrict__ wv2,
                                     u64* a1, u64* aq) {
    u64 u = pack2(vx, vy);
    float s2  = fmaf(vy, vy, vx * vx);
    float pxy = vx * vy;
    u64 q = pack2(s2, pxy);
    #pragma unroll
    for (int i = 0; i < R; i++) {
        int k = tt - i;
        if (k >= 0 && k < KS) {
            int wi = WIDX(k);
            a1[i] = fma2(wv2[wi], u, a1[i]);
            aq[i] = fma2(wv2[wi], q, aq[i]);
        }
    }
}

/* one vertical-conv task: column m (tile-local), output rows [rg, rg+R) */
template<int R>
__device__ __forceinline__ void run_task(int m, int rg, int oh0, int ow0,
                                         const float* __restrict__ xp,
                                         const float* __restrict__ yp,
                                         const u64* __restrict__ wv2,
                                         float2* s_v1, float2* s_vq) {
    const int NR = R + KS - 1;
    int gc = ow0 + m - HALO;
    bool colok = (unsigned)gc < (unsigned)IMG;
    int r0 = oh0 + rg - HALO;
    bool rowok = (r0 >= 0) && (r0 + NR <= IMG);
    const float* xb = xp + (ptrdiff_t)r0 * IMG + gc;
    const float* yb = yp + (ptrdiff_t)r0 * IMG + gc;

    u64 a1[R], aq[R];
    #pragma unroll
    for (int i = 0; i < R; i++) { a1[i] = 0ull; aq[i] = 0ull; }

    if (colok && rowok) {
        #pragma unroll
        for (int tt = 0; tt < NR; tt++)            // unpredicated fast path
            vacc<R>(__ldg(xb + tt * IMG), __ldg(yb + tt * IMG), tt, wv2, a1, aq);
    } else {
        #pragma unroll
        for (int tt = 0; tt < NR; tt++) {
            int gr = r0 + tt;
            float vx = 0.f, vy = 0.f;
            if (colok && (unsigned)gr < (unsigned)IMG) {
                vx = __ldg(xb + tt * IMG);
                vy = __ldg(yb + tt * IMG);
            }
            vacc<R>(vx, vy, tt, wv2, a1, aq);
        }
    }
    #pragma unroll
    for (int i = 0; i < R; i++) {
        *reinterpret_cast<u64*>(&s_v1[(rg + i) * S2 + m]) = a1[i];
        *reinterpret_cast<u64*>(&s_vq[(rg + i) * S2 + m]) = aq[i];
    }
}

__global__ __launch_bounds__(NTHREADS, 4)
void ssim_main(const float* __restrict__ x, const float* __restrict__ y) {
    float2* s_v1 = smem_dyn;                  // [TH][S2] (sum_x, sum_y)
    float2* s_vq = s_v1 + TH * S2;            // [TH][S2] (sum_{x^2+y^2}, sum_xy)

    const int tid = threadIdx.x;
    const int plane = blockIdx.z;             // 64 = 32 batch * 2 chan (NCHW)
    const int ch = plane & 1;
    const int oh0 = blockIdx.y * TH;
    const int ow0 = blockIdx.x * TW;
    const float* xp = x + (size_t)plane * IMG * IMG;
    const float* yp = y + (size_t)plane * IMG * IMG;

    u64 wv2[6];
    #pragma unroll
    for (int k = 0; k < 6; k++) { float w = __ldg(&g_wv[ch][k]); wv2[k] = pack2(w, w); }

    // ---- stage 1: 276 tasks = 256 RG8 (1:1 threads) + 20 split as 40 RG4 ----
    {
        int m   = (tid < COLS) ? tid : tid - COLS;   // cols 0..137 / 0..117
        int rgi = (tid < COLS) ? 0 : 1;
        run_task<8>(m, rgi * 8, oh0, ow0, xp, yp, wv2, s_v1, s_vq);

        if (tid < 40) {                               // leftover cols 118..137, rgi=1
            int m2  = (COLS - 20) + (tid >> 1);
            int rg2 = 8 + (tid & 1) * 4;
            run_task<4>(m2, rg2, oh0, ow0, xp, yp, wv2, s_v1, s_vq);
        }
    }

    __syncthreads();

    // ---- stage 2: horizontal conv, 8 px per thread ----
    u64 wh2[6];
    #pragma unroll
    for (int k = 0; k < 6; k++) { float w = __ldg(&g_wh[ch][k]); wh2[k] = pack2(w, w); }

    const int row = tid & 15;                 // 16 rows; half-warp phases conflict-free
    const int c0 = (tid >> 4) * 8;            // 16 col groups * 8 = 128
    const float C1 = 1e-4f, C2 = 9e-4f;
    float lsum = 0.f;

    u64 h1[8], hq[8];
    #pragma unroll
    for (int p = 0; p < 8; p++) { h1[p] = 0ull; hq[p] = 0ull; }

    #pragma unroll
    for (int j = 0; j < 8 + KS - 1; j++) {    // 18 input cols shared across 8 px
        u64 b1 = *reinterpret_cast<const u64*>(&s_v1[row * S2 + c0 + j]);
        u64 bq = *reinterpret_cast<const u64*>(&s_vq[row * S2 + c0 + j]);
        #pragma unroll
        for (int p = 0; p < 8; p++) {
            int k = j - p;
            if (k >= 0 && k < KS) {
                int wi = WIDX(k);
                h1[p] = fma2(wh2[wi], b1, h1[p]);
                hq[p] = fma2(wh2[wi], bq, hq[p]);
            }
        }
    }

    // ---- epilogue: SSIM per pixel ----
    #pragma unroll
    for (int p = 0; p < 8; p++) {
        float mux, muy; unpack2(h1[p], mux, muy);
        float es, exy;  unpack2(hq[p], es, exy);     // es = E[x^2+y^2]
        float muxy = mux * muy;
        float sxy  = fmaf(-mux, muy, exy);
        float na   = fmaf(muxy, 2.0f, C1);
        float nb   = fmaf(sxy,  2.0f, C2);
        float m2   = fmaf(mux, mux, muy * muy);
        float dena = m2 + C1;
        float denb = (es - m2) + C2;
        lsum += __fdividef(na * nb, dena * denb);
    }

    // ---- reduction: warp -> block -> one double atomic ----
    #pragma unroll
    for (int o = 16; o > 0; o >>= 1) lsum += __shfl_xor_sync(0xffffffffu, lsum, o);
    __shared__ float wsum[NTHREADS / 32];
    if ((tid & 31) == 0) wsum[tid >> 5] = lsum;
    __syncthreads();
    if (tid == 0) {
        float b = 0.f;
        #pragma unroll
        for (int w = 0; w < NTHREADS / 32; w++) b += wsum[w];
        atomicAdd(&g_accum, (double)b);
    }
}

__global__ void finalize_kernel(float* __restrict__ out) {
    if (threadIdx.x == 0) {
        out[0] = 1.0f - (float)(g_accum * (1.0 / (32.0 * 2.0 * 512.0 * 512.0)));
    }
}

extern "C" void kernel_launch(void* const* d_in, const int* in_sizes, int n_in,
                              void* d_out, int out_size) {
    const float* x = (const float*)d_in[0];
    const float* y = (const float*)d_in[1];
    const float* kern = (const float*)d_in[2];
    float* out = (float*)d_out;

    prep_kernel<<<1, 64>>>(kern);
    dim3 grid(IMG / TW, IMG / TH, 64);
    ssim_main<<<grid, NTHREADS, SMEM_BYTES>>>(x, y);
    finalize_kernel<<<1, 32>>>(out);
}